// round 15
// baseline (speedup 1.0000x reference)
#include <cuda_runtime.h>
#include <math.h>

#define T_STEPS 4096
#define BATCH   32
#define DIN     256
#define HID     256
#define GATES   1024
#define OUTD    512
#define CL_SZ   8
#define NBLK    128

__device__ float g_xz_f[(size_t)T_STEPS * BATCH * GATES];
__device__ float g_xz_b[(size_t)T_STEPS * BATCH * GATES];
__device__ float g_houts[(size_t)T_STEPS * BATCH * 2 * HID];

__device__ __forceinline__ float sigf(float x)  { return 1.0f / (1.0f + __expf(-x)); }
__device__ __forceinline__ float tanhf_(float x){ return 1.0f - 2.0f / (__expf(2.0f * x) + 1.0f); }

__device__ __forceinline__ unsigned long long ffma2(
    unsigned long long a, unsigned long long b, unsigned long long c) {
    unsigned long long d;
    asm("fma.rn.f32x2 %0, %1, %2, %3;" : "=l"(d) : "l"(a), "l"(b), "l"(c));
    return d;
}
__device__ __forceinline__ unsigned long long bcast2(float a) {
    unsigned long long d;
    asm("mov.b64 %0, {%1, %1};" : "=l"(d) : "f"(a));
    return d;
}
__device__ __forceinline__ unsigned smem_u32(const void* p) {
    return (unsigned)__cvta_generic_to_shared(p);
}
__device__ __forceinline__ void mbar_wait_cl(unsigned addr, unsigned parity) {
    asm volatile(
        "{\n\t.reg .pred P;\n"
        "LW%=:\n\t"
        "mbarrier.try_wait.parity.acquire.cluster.shared::cta.b64 P, [%0], %1, 0x989680;\n\t"
        "@P bra LD%=;\n\t"
        "bra LW%=;\n"
        "LD%=:\n\t}"
        :: "r"(addr), "r"(parity) : "memory");
}

#define CLUSTER_SYNC() do { \
    asm volatile("barrier.cluster.arrive.aligned;" ::: "memory"); \
    asm volatile("barrier.cluster.wait.aligned;"   ::: "memory"); \
} while (0)

// dummy launch to align ncu's capture window (-s 5 -c 1) onto k_recur
__global__ void k_prof_pad() {}

// ---------------- GEMM 1: xz = x @ Wx + bias (unchanged, passing) -----------
__global__ void __launch_bounds__(256) k_gemm_xz(
    const float* __restrict__ A, const float* __restrict__ W,
    const float* __restrict__ bias, float* __restrict__ C)
{
    __shared__ float As[8][128];
    __shared__ float Bs[8][128];
    const int tid = threadIdx.x;
    const int n0 = blockIdx.x << 7, m0 = blockIdx.y << 7;
    const int am = tid >> 1, ak = (tid & 1) << 2;
    const int bk = tid >> 5, bn = (tid & 31) << 2;
    const int ty = tid >> 4, tx = tid & 15;
    unsigned long long acc2[8][4] = {};

    for (int k0 = 0; k0 < DIN; k0 += 8) {
        float4 av = *(const float4*)(A + (size_t)(m0 + am) * DIN + k0 + ak);
        float4 bv = *(const float4*)(W + (size_t)(k0 + bk) * GATES + n0 + bn);
        __syncthreads();
        As[ak + 0][am] = av.x; As[ak + 1][am] = av.y;
        As[ak + 2][am] = av.z; As[ak + 3][am] = av.w;
        *(float4*)&Bs[bk][bn] = bv;
        __syncthreads();
#pragma unroll
        for (int kk = 0; kk < 8; kk++) {
            float ar[8];
            *(float4*)&ar[0] = *(const float4*)&As[kk][(ty << 3) + 0];
            *(float4*)&ar[4] = *(const float4*)&As[kk][(ty << 3) + 4];
            union { float4 f; unsigned long long u[2]; } B0, B1;
            B0.f = *(const float4*)&Bs[kk][(tx << 3) + 0];
            B1.f = *(const float4*)&Bs[kk][(tx << 3) + 4];
#pragma unroll
            for (int r = 0; r < 8; r++) {
                unsigned long long a2 = bcast2(ar[r]);
                acc2[r][0] = ffma2(a2, B0.u[0], acc2[r][0]);
                acc2[r][1] = ffma2(a2, B0.u[1], acc2[r][1]);
                acc2[r][2] = ffma2(a2, B1.u[0], acc2[r][2]);
                acc2[r][3] = ffma2(a2, B1.u[1], acc2[r][3]);
            }
        }
    }
    float bi[8];
    *(float4*)&bi[0] = *(const float4*)(bias + n0 + (tx << 3) + 0);
    *(float4*)&bi[4] = *(const float4*)(bias + n0 + (tx << 3) + 4);
#pragma unroll
    for (int r = 0; r < 8; r++) {
        int m = m0 + (ty << 3) + r;
        int t = m & (T_STEPS - 1), b = m >> 12;
        float* dst = C + (size_t)(t * BATCH + b) * GATES + n0 + (tx << 3);
        union { unsigned long long u; float f[2]; } U;
        float o[8];
#pragma unroll
        for (int c4 = 0; c4 < 4; c4++) {
            U.u = acc2[r][c4];
            o[2 * c4 + 0] = U.f[0] + bi[2 * c4 + 0];
            o[2 * c4 + 1] = U.f[1] + bi[2 * c4 + 1];
        }
        *(float4*)(dst + 0) = *(float4*)&o[0];
        *(float4*)(dst + 4) = *(float4*)&o[4];
    }
}

// ---------------- GEMM 2: out = relu(h_cat) @ W_dense + b (unchanged) ------
__global__ void __launch_bounds__(256) k_gemm_dense(
    const float* __restrict__ W, const float* __restrict__ bias,
    float* __restrict__ out)
{
    __shared__ float As[8][128];
    __shared__ float Bs[8][128];
    const int tid = threadIdx.x;
    const int n0 = blockIdx.x << 7, m0 = blockIdx.y << 7;
    const int am = tid >> 1, ak = (tid & 1) << 2;
    const int bk = tid >> 5, bn = (tid & 31) << 2;
    const int ty = tid >> 4, tx = tid & 15;
    unsigned long long acc2[8][4] = {};

    for (int k0 = 0; k0 < 2 * HID; k0 += 8) {
        float4 av = *(const float4*)(g_houts + (size_t)(m0 + am) * (2 * HID) + k0 + ak);
        av.x = fmaxf(av.x, 0.f); av.y = fmaxf(av.y, 0.f);
        av.z = fmaxf(av.z, 0.f); av.w = fmaxf(av.w, 0.f);
        float4 bv = *(const float4*)(W + (size_t)(k0 + bk) * OUTD + n0 + bn);
        __syncthreads();
        As[ak + 0][am] = av.x; As[ak + 1][am] = av.y;
        As[ak + 2][am] = av.z; As[ak + 3][am] = av.w;
        *(float4*)&Bs[bk][bn] = bv;
        __syncthreads();
#pragma unroll
        for (int kk = 0; kk < 8; kk++) {
            float ar[8];
            *(float4*)&ar[0] = *(const float4*)&As[kk][(ty << 3) + 0];
            *(float4*)&ar[4] = *(const float4*)&As[kk][(ty << 3) + 4];
            union { float4 f; unsigned long long u[2]; } B0, B1;
            B0.f = *(const float4*)&Bs[kk][(tx << 3) + 0];
            B1.f = *(const float4*)&Bs[kk][(tx << 3) + 4];
#pragma unroll
            for (int r = 0; r < 8; r++) {
                unsigned long long a2 = bcast2(ar[r]);
                acc2[r][0] = ffma2(a2, B0.u[0], acc2[r][0]);
                acc2[r][1] = ffma2(a2, B0.u[1], acc2[r][1]);
                acc2[r][2] = ffma2(a2, B1.u[0], acc2[r][2]);
                acc2[r][3] = ffma2(a2, B1.u[1], acc2[r][3]);
            }
        }
    }
    float bi[8];
    *(float4*)&bi[0] = *(const float4*)(bias + n0 + (tx << 3) + 0);
    *(float4*)&bi[4] = *(const float4*)(bias + n0 + (tx << 3) + 4);
#pragma unroll
    for (int r = 0; r < 8; r++) {
        int m = m0 + (ty << 3) + r;
        int b = m & 31, t = m >> 5;
        float* dst = out + ((size_t)b * T_STEPS + t) * OUTD + n0 + (tx << 3);
        union { unsigned long long u; float f[2]; } U;
        float o[8];
#pragma unroll
        for (int c4 = 0; c4 < 4; c4++) {
            U.u = acc2[r][c4];
            o[2 * c4 + 0] = U.f[0] + bi[2 * c4 + 0];
            o[2 * c4 + 1] = U.f[1] + bi[2 * c4 + 1];
        }
        *(float4*)(dst + 0) = *(float4*)&o[0];
        *(float4*)(dst + 4) = *(float4*)&o[4];
    }
}

// ---------------- Recurrence: fully warp-local step, NO __syncthreads ------
// 16 clusters x 8 CTAs x 512 thr. Warp w owns local cols {2w, 2w+1}.
// Lane l = col*16 + g*4 + q handles (col, gate g, 64-k quarter q), BOTH
// batches. Per step per warp: mbar wait -> 32 LDS.128 + 64 FFMA2 ->
// 2 shfl.bfly (k-reduce) + xz -> per-lane activation -> 8 shfl gate-gather
// -> 4 sender lanes {0,8,16,24} do c/h update and 8 st.async each.
// Cross-warp/CTA ordering carried entirely by the exchange mbarrier:
// a buffer is only overwritten by exchange gs+1 stores, issued after
// exchange gs completed, which requires every warp's sends (which follow
// that warp's reads). Exchange = 2-deep ping-pong as in R10.
__global__ void __cluster_dims__(CL_SZ, 1, 1) __launch_bounds__(512, 1) k_recur(
    const float* __restrict__ carry_c, const float* __restrict__ carry_h,
    const float* __restrict__ Wh_f, const float* __restrict__ Wh_b)
{
    __shared__ float h_s[2][2][HID];           // [buf][batch][k], buf stride 2048B
    __shared__ unsigned long long mb[2];       // 8 B apart

    const int tid   = threadIdx.x;
    const int w     = tid >> 5, l = tid & 31;
    const int rank  = blockIdx.x & (CL_SZ - 1);
    const int b0    = (blockIdx.x >> 3) << 1;
    const int jbase = rank << 5;

    const int col = (l >> 4) & 1;              // which of the warp's 2 cols
    const int g   = (l >> 2) & 3;              // gate
    const int q   = l & 3;                     // 64-k quarter
    const int jl  = (w << 1) | col;            // local h-col 0..31
    const int gc  = (g << 8) + jbase + jl;     // global gate col

    const bool issend = ((l & 7) == 0);        // lanes 0,8,16,24
    const int  Xs = (l >> 3) & 1;              // sender's batch
    const unsigned TXB = CL_SZ * 64u * 4u;     // 2048 bytes per exchange

    h_s[0][tid >> 8][tid & 255] =
        carry_h[(size_t)(b0 + (tid >> 8)) * HID + (tid & 255)];

    if (tid == 0) {
        asm volatile("mbarrier.init.shared.b64 [%0], %1;"
                     :: "r"(smem_u32(&mb[0])), "r"(1) : "memory");
        asm volatile("mbarrier.init.shared.b64 [%0], %1;"
                     :: "r"(smem_u32(&mb[1])), "r"(1) : "memory");
    }

    float c_reg = 0.f;
    unsigned rem_h0[CL_SZ];   // peer addr of h_s[0][Xs][jbase+jl]; buf1=+2048
    unsigned rem_mb0[CL_SZ];  // peer addr of mb[0]; mb[1]=+8
    if (issend) {
        c_reg = carry_c[(size_t)(b0 + Xs) * HID + jbase + jl];
        unsigned lh = smem_u32(&h_s[0][Xs][jbase + jl]);
        unsigned lm = smem_u32(&mb[0]);
#pragma unroll
        for (int p = 0; p < CL_SZ; p++) {
            asm("mapa.shared::cluster.u32 %0, %1, %2;"
                : "=r"(rem_h0[p]) : "r"(lh), "r"(p));
            asm("mapa.shared::cluster.u32 %0, %1, %2;"
                : "=r"(rem_mb0[p]) : "r"(lm), "r"(p));
        }
    }
    __syncthreads();
    CLUSTER_SYNC();   // mbars + h bufs visible cluster-wide before step 0

    const unsigned mb0a = smem_u32(&mb[0]);

    int gs = 0;
    for (int dir = 0; dir < 2; dir++) {
        const float* __restrict__ Wh = dir ? Wh_b : Wh_f;
        const float* __restrict__ xz = dir ? g_xz_b : g_xz_f;
        const int half = dir ? HID : 0;

        // register-resident weights: 64 k (quarter q) x 1 gate-col (gc)
        unsigned long long w2[32];
#pragma unroll
        for (int kk = 0; kk < 32; kk++) {
            union { float f[2]; unsigned long long u; } P;
            P.f[0] = Wh[(size_t)((q << 6) + 2 * kk + 0) * GATES + gc];
            P.f[1] = Wh[(size_t)((q << 6) + 2 * kk + 1) * GATES + gc];
            w2[kk] = P.u;
        }

        // xz prefetch (both batches), refreshed 1 step ahead
        float xz0, xz1;
        {
            const int t0 = dir ? (T_STEPS - 1) : 0;
            xz0 = __ldcg(xz + ((size_t)t0 * BATCH + b0 + 0) * GATES + gc);
            xz1 = __ldcg(xz + ((size_t)t0 * BATCH + b0 + 1) * GATES + gc);
        }

        for (int s = 0; s < T_STEPS; s++, gs++) {
            const int t   = dir ? (T_STEPS - 1 - s) : s;
            const int cur = gs & 1, nxt = cur ^ 1;

            if (gs > 0) {   // wait for exchange gs-1 (all 2048 B landed)
                const int e = gs - 1;
                mbar_wait_cl(mb0a + (unsigned)((e & 1) << 3),
                             (unsigned)((e >> 1) & 1));
            }
            if (tid == 0)
                asm volatile(
                    "mbarrier.arrive.expect_tx.shared.b64 _, [%0], %1;"
                    :: "r"(mb0a + (unsigned)((gs & 1) << 3)), "r"(TXB)
                    : "memory");

            // dot products over this lane's 64-k quarter, both batches
            unsigned long long a0 = 0ull, a1 = 0ull, b0a = 0ull, b1a = 0ull;
            {
                const float4* h0 = (const float4*)&h_s[cur][0][q << 6];
                const float4* h1 = (const float4*)&h_s[cur][1][q << 6];
#pragma unroll
                for (int i = 0; i < 8; i++) {
                    union { float4 f; unsigned long long u[2]; } U0, U1;
                    U0.f = h0[2 * i];     U1.f = h1[2 * i];
                    a0  = ffma2(U0.u[0], w2[4 * i + 0], a0);
                    a0  = ffma2(U0.u[1], w2[4 * i + 1], a0);
                    a1  = ffma2(U1.u[0], w2[4 * i + 0], a1);
                    a1  = ffma2(U1.u[1], w2[4 * i + 1], a1);
                    U0.f = h0[2 * i + 1]; U1.f = h1[2 * i + 1];
                    b0a = ffma2(U0.u[0], w2[4 * i + 2], b0a);
                    b0a = ffma2(U0.u[1], w2[4 * i + 3], b0a);
                    b1a = ffma2(U1.u[0], w2[4 * i + 2], b1a);
                    b1a = ffma2(U1.u[1], w2[4 * i + 3], b1a);
                }
            }
            float z0, z1;
            {
                union { unsigned long long u; float f[2]; } A, B;
                A.u = a0; B.u = b0a;
                z0 = (A.f[0] + A.f[1]) + (B.f[0] + B.f[1]);
                A.u = a1; B.u = b1a;
                z1 = (A.f[0] + A.f[1]) + (B.f[0] + B.f[1]);
            }
            // k-reduce across q (lane bits 0-1)
            z0 += __shfl_xor_sync(0xffffffffu, z0, 1);
            z0 += __shfl_xor_sync(0xffffffffu, z0, 2);
            z1 += __shfl_xor_sync(0xffffffffu, z1, 1);
            z1 += __shfl_xor_sync(0xffffffffu, z1, 2);
            z0 += xz0;
            z1 += xz1;
            // prefetch next step's xz
            if (s + 1 < T_STEPS) {
                const int tn = dir ? (T_STEPS - 2 - s) : (s + 1);
                xz0 = __ldcg(xz + ((size_t)tn * BATCH + b0 + 0) * GATES + gc);
                xz1 = __ldcg(xz + ((size_t)tn * BATCH + b0 + 1) * GATES + gc);
            }

            // per-lane activation for this gate (tanh for g==2)
            const float zi0 = (g == 2) ? (z0 + z0) : z0;
            const float zi1 = (g == 2) ? (z1 + z1) : z1;
            float act0 = sigf(zi0);
            float act1 = sigf(zi1);
            if (g == 2) { act0 = 2.f * act0 - 1.f; act1 = 2.f * act1 - 1.f; }

            // gather 4 gates to sender lanes (sources: same col, q=0 slot)
            const int cb = l & 16;
            const float i0 = __shfl_sync(0xffffffffu, act0, cb + 0);
            const float f0 = __shfl_sync(0xffffffffu, act0, cb + 4);
            const float g0 = __shfl_sync(0xffffffffu, act0, cb + 8);
            const float o0 = __shfl_sync(0xffffffffu, act0, cb + 12);
            const float i1 = __shfl_sync(0xffffffffu, act1, cb + 0);
            const float f1 = __shfl_sync(0xffffffffu, act1, cb + 4);
            const float g1 = __shfl_sync(0xffffffffu, act1, cb + 8);
            const float o1 = __shfl_sync(0xffffffffu, act1, cb + 12);

            if (issend) {
                const float gi = Xs ? i1 : i0;
                const float gf = Xs ? f1 : f0;
                const float gg = Xs ? g1 : g0;
                const float go = Xs ? o1 : o0;
                c_reg = fmaf(gf, c_reg, gi * gg);
                const float h = go * tanhf_(c_reg);
                const unsigned hval = __float_as_uint(h);
                const unsigned hoff = (unsigned)(nxt << 11);     // buf 2048B
                const unsigned moff = (unsigned)((gs & 1) << 3); // mbar 8B
#pragma unroll
                for (int p = 0; p < CL_SZ; p++)
                    asm volatile(
                        "st.async.shared::cluster.mbarrier::complete_tx::bytes.b32 "
                        "[%0], %1, [%2];"
                        :: "r"(rem_h0[p] + hoff), "r"(hval),
                           "r"(rem_mb0[p] + moff) : "memory");
                g_houts[((size_t)t * BATCH + b0 + Xs) * (2 * HID)
                        + half + jbase + jl] = h;
            }
        }
    }
    // drain the final exchange so no in-flight st.async targets exiting CTAs
    {
        const int e = 2 * T_STEPS - 1;
        mbar_wait_cl(mb0a + (unsigned)((e & 1) << 3), (unsigned)((e >> 1) & 1));
    }
    CLUSTER_SYNC();
}

// ---------------- launch ----------------------------------------------------
extern "C" void kernel_launch(void* const* d_in, const int* in_sizes, int n_in,
                              void* d_out, int out_size) {
    const float* carry_c = (const float*)d_in[0];
    const float* carry_h = (const float*)d_in[1];
    const float* x       = (const float*)d_in[2];
    const float* Wx_f    = (const float*)d_in[3];
    const float* Wh_f    = (const float*)d_in[4];
    const float* b_f     = (const float*)d_in[5];
    const float* Wx_b    = (const float*)d_in[6];
    const float* Wh_b    = (const float*)d_in[7];
    const float* b_b     = (const float*)d_in[8];
    const float* W_dense = (const float*)d_in[9];
    const float* b_dense = (const float*)d_in[10];
    float* out = (float*)d_out;

    float* xz_f; cudaGetSymbolAddress((void**)&xz_f, g_xz_f);
    float* xz_b; cudaGetSymbolAddress((void**)&xz_b, g_xz_b);

    k_prof_pad<<<1, 1>>>();   // aligns ncu capture window onto k_recur

    dim3 g1(GATES / 128, (BATCH * T_STEPS) / 128);
    k_gemm_xz<<<g1, 256>>>(x, Wx_f, b_f, xz_f);
    k_gemm_xz<<<g1, 256>>>(x, Wx_b, b_b, xz_b);

    k_recur<<<NBLK, 512>>>(carry_c, carry_h, Wh_f, Wh_b);

    dim3 g2(OUTD / 128, (BATCH * T_STEPS) / 128);
    k_gemm_dense<<<g2, 256>>>(W_dense, b_dense, out);
}

// round 16
// speedup vs baseline: 3.2572x; 3.2572x over previous
#include <cuda_runtime.h>
#include <math.h>

#define T_STEPS 4096
#define BATCH   32
#define DIN     256
#define HID     256
#define GATES   1024
#define OUTD    512
#define CL_SZ   8
#define NBLK    128

__device__ float g_xz_f[(size_t)T_STEPS * BATCH * GATES];
__device__ float g_xz_b[(size_t)T_STEPS * BATCH * GATES];
__device__ float g_houts[(size_t)T_STEPS * BATCH * 2 * HID];

__device__ __forceinline__ float sigf(float x)  { return 1.0f / (1.0f + __expf(-x)); }
__device__ __forceinline__ float tanhf_(float x){ return 1.0f - 2.0f / (__expf(2.0f * x) + 1.0f); }

__device__ __forceinline__ unsigned long long ffma2(
    unsigned long long a, unsigned long long b, unsigned long long c) {
    unsigned long long d;
    asm("fma.rn.f32x2 %0, %1, %2, %3;" : "=l"(d) : "l"(a), "l"(b), "l"(c));
    return d;
}
__device__ __forceinline__ unsigned long long bcast2(float a) {
    unsigned long long d;
    asm("mov.b64 %0, {%1, %1};" : "=l"(d) : "f"(a));
    return d;
}
__device__ __forceinline__ unsigned smem_u32(const void* p) {
    return (unsigned)__cvta_generic_to_shared(p);
}
__device__ __forceinline__ void mbar_wait_cl(unsigned addr, unsigned parity) {
    asm volatile(
        "{\n\t.reg .pred P;\n"
        "LW%=:\n\t"
        "mbarrier.try_wait.parity.acquire.cluster.shared::cta.b64 P, [%0], %1, 0x989680;\n\t"
        "@P bra LD%=;\n\t"
        "bra LW%=;\n"
        "LD%=:\n\t}"
        :: "r"(addr), "r"(parity) : "memory");
}

#define CLUSTER_SYNC() do { \
    asm volatile("barrier.cluster.arrive.aligned;" ::: "memory"); \
    asm volatile("barrier.cluster.wait.aligned;"   ::: "memory"); \
} while (0)

// dummy launch to align ncu's capture window (-s 5 -c 1) onto k_recur
__global__ void k_prof_pad() {}

// ---------------- GEMM 1: xz = x @ Wx + bias (unchanged, passing) -----------
__global__ void __launch_bounds__(256) k_gemm_xz(
    const float* __restrict__ A, const float* __restrict__ W,
    const float* __restrict__ bias, float* __restrict__ C)
{
    __shared__ float As[8][128];
    __shared__ float Bs[8][128];
    const int tid = threadIdx.x;
    const int n0 = blockIdx.x << 7, m0 = blockIdx.y << 7;
    const int am = tid >> 1, ak = (tid & 1) << 2;
    const int bk = tid >> 5, bn = (tid & 31) << 2;
    const int ty = tid >> 4, tx = tid & 15;
    unsigned long long acc2[8][4] = {};

    for (int k0 = 0; k0 < DIN; k0 += 8) {
        float4 av = *(const float4*)(A + (size_t)(m0 + am) * DIN + k0 + ak);
        float4 bv = *(const float4*)(W + (size_t)(k0 + bk) * GATES + n0 + bn);
        __syncthreads();
        As[ak + 0][am] = av.x; As[ak + 1][am] = av.y;
        As[ak + 2][am] = av.z; As[ak + 3][am] = av.w;
        *(float4*)&Bs[bk][bn] = bv;
        __syncthreads();
#pragma unroll
        for (int kk = 0; kk < 8; kk++) {
            float ar[8];
            *(float4*)&ar[0] = *(const float4*)&As[kk][(ty << 3) + 0];
            *(float4*)&ar[4] = *(const float4*)&As[kk][(ty << 3) + 4];
            union { float4 f; unsigned long long u[2]; } B0, B1;
            B0.f = *(const float4*)&Bs[kk][(tx << 3) + 0];
            B1.f = *(const float4*)&Bs[kk][(tx << 3) + 4];
#pragma unroll
            for (int r = 0; r < 8; r++) {
                unsigned long long a2 = bcast2(ar[r]);
                acc2[r][0] = ffma2(a2, B0.u[0], acc2[r][0]);
                acc2[r][1] = ffma2(a2, B0.u[1], acc2[r][1]);
                acc2[r][2] = ffma2(a2, B1.u[0], acc2[r][2]);
                acc2[r][3] = ffma2(a2, B1.u[1], acc2[r][3]);
            }
        }
    }
    float bi[8];
    *(float4*)&bi[0] = *(const float4*)(bias + n0 + (tx << 3) + 0);
    *(float4*)&bi[4] = *(const float4*)(bias + n0 + (tx << 3) + 4);
#pragma unroll
    for (int r = 0; r < 8; r++) {
        int m = m0 + (ty << 3) + r;
        int t = m & (T_STEPS - 1), b = m >> 12;
        float* dst = C + (size_t)(t * BATCH + b) * GATES + n0 + (tx << 3);
        union { unsigned long long u; float f[2]; } U;
        float o[8];
#pragma unroll
        for (int c4 = 0; c4 < 4; c4++) {
            U.u = acc2[r][c4];
            o[2 * c4 + 0] = U.f[0] + bi[2 * c4 + 0];
            o[2 * c4 + 1] = U.f[1] + bi[2 * c4 + 1];
        }
        *(float4*)(dst + 0) = *(float4*)&o[0];
        *(float4*)(dst + 4) = *(float4*)&o[4];
    }
}

// ---------------- GEMM 2: out = relu(h_cat) @ W_dense + b (unchanged) ------
__global__ void __launch_bounds__(256) k_gemm_dense(
    const float* __restrict__ W, const float* __restrict__ bias,
    float* __restrict__ out)
{
    __shared__ float As[8][128];
    __shared__ float Bs[8][128];
    const int tid = threadIdx.x;
    const int n0 = blockIdx.x << 7, m0 = blockIdx.y << 7;
    const int am = tid >> 1, ak = (tid & 1) << 2;
    const int bk = tid >> 5, bn = (tid & 31) << 2;
    const int ty = tid >> 4, tx = tid & 15;
    unsigned long long acc2[8][4] = {};

    for (int k0 = 0; k0 < 2 * HID; k0 += 8) {
        float4 av = *(const float4*)(g_houts + (size_t)(m0 + am) * (2 * HID) + k0 + ak);
        av.x = fmaxf(av.x, 0.f); av.y = fmaxf(av.y, 0.f);
        av.z = fmaxf(av.z, 0.f); av.w = fmaxf(av.w, 0.f);
        float4 bv = *(const float4*)(W + (size_t)(k0 + bk) * OUTD + n0 + bn);
        __syncthreads();
        As[ak + 0][am] = av.x; As[ak + 1][am] = av.y;
        As[ak + 2][am] = av.z; As[ak + 3][am] = av.w;
        *(float4*)&Bs[bk][bn] = bv;
        __syncthreads();
#pragma unroll
        for (int kk = 0; kk < 8; kk++) {
            float ar[8];
            *(float4*)&ar[0] = *(const float4*)&As[kk][(ty << 3) + 0];
            *(float4*)&ar[4] = *(const float4*)&As[kk][(ty << 3) + 4];
            union { float4 f; unsigned long long u[2]; } B0, B1;
            B0.f = *(const float4*)&Bs[kk][(tx << 3) + 0];
            B1.f = *(const float4*)&Bs[kk][(tx << 3) + 4];
#pragma unroll
            for (int r = 0; r < 8; r++) {
                unsigned long long a2 = bcast2(ar[r]);
                acc2[r][0] = ffma2(a2, B0.u[0], acc2[r][0]);
                acc2[r][1] = ffma2(a2, B0.u[1], acc2[r][1]);
                acc2[r][2] = ffma2(a2, B1.u[0], acc2[r][2]);
                acc2[r][3] = ffma2(a2, B1.u[1], acc2[r][3]);
            }
        }
    }
    float bi[8];
    *(float4*)&bi[0] = *(const float4*)(bias + n0 + (tx << 3) + 0);
    *(float4*)&bi[4] = *(const float4*)(bias + n0 + (tx << 3) + 4);
#pragma unroll
    for (int r = 0; r < 8; r++) {
        int m = m0 + (ty << 3) + r;
        int b = m & 31, t = m >> 5;
        float* dst = out + ((size_t)b * T_STEPS + t) * OUTD + n0 + (tx << 3);
        union { unsigned long long u; float f[2]; } U;
        float o[8];
#pragma unroll
        for (int c4 = 0; c4 < 4; c4++) {
            U.u = acc2[r][c4];
            o[2 * c4 + 0] = U.f[0] + bi[2 * c4 + 0];
            o[2 * c4 + 1] = U.f[1] + bi[2 * c4 + 1];
        }
        *(float4*)(dst + 0) = *(float4*)&o[0];
        *(float4*)(dst + 4) = *(float4*)&o[4];
    }
}

// ---------------- Recurrence: R10 + PER-SOURCE mbarriers --------------------
// mb[src][par]: completed by source CTA src's 64 floats (256 B). kseg warps
// wait only their two source CTAs (2*kseg, 2*kseg+1), with the half-dot
// computed between the two waits. Producers unchanged (send after BAR ->
// bounded 1-step skew, same as R10). Lanes 0-7 re-arm mb[r][gs&1] each step
// after verifying its gs-2 phase passed.
__global__ void __cluster_dims__(CL_SZ, 1, 1) __launch_bounds__(512, 1) k_recur(
    const float* __restrict__ carry_c, const float* __restrict__ carry_h,
    const float* __restrict__ Wh_f, const float* __restrict__ Wh_b)
{
    __shared__ float h_s[2][2][HID];           // ping-pong: 2048 B apart
    __shared__ float p_s[4][2][128];
    __shared__ unsigned long long mb[8][2];    // [src][parity]

    const int tid   = threadIdx.x;
    const int rank  = blockIdx.x & (CL_SZ - 1);
    const int b0    = (blockIdx.x >> 3) << 1;
    const int jbase = rank << 5;

    const int kseg = tid >> 7;
    const int col  = tid & 127;
    const int gate = col >> 5, jl = col & 31;
    const int gc   = (gate << 8) + jbase + jl;

    const bool isprod = (tid >= 448);          // warps 14-15
    const int  pt = tid - 448;
    const int  bp = pt >> 5, jp = pt & 31;
    const unsigned TXB = 64u * 4u;             // 256 B per source barrier

    h_s[0][tid >> 8][tid & 255] =
        carry_h[(size_t)(b0 + (tid >> 8)) * HID + (tid & 255)];

    if (tid == 0) {
#pragma unroll
        for (int i = 0; i < 16; i++)
            asm volatile("mbarrier.init.shared.b64 [%0], %1;"
                         :: "r"(smem_u32(&mb[0][0]) + (unsigned)(i << 3)),
                            "r"(1) : "memory");
    }

    float c_reg = 0.f;
    unsigned rem_h0[CL_SZ];   // peer addr of h_s[0][bp][jbase+jp]; buf1 = +2048
    unsigned rem_mb0[CL_SZ];  // peer addr of mb[rank][0]; parity = +8
    if (isprod) {
        c_reg = carry_c[(size_t)(b0 + bp) * HID + jbase + jp];
        unsigned lh = smem_u32(&h_s[0][bp][jbase + jp]);
        unsigned lm = smem_u32(&mb[rank][0]);
#pragma unroll
        for (int p = 0; p < CL_SZ; p++) {
            asm("mapa.shared::cluster.u32 %0, %1, %2;"
                : "=r"(rem_h0[p]) : "r"(lh), "r"(p));
            asm("mapa.shared::cluster.u32 %0, %1, %2;"
                : "=r"(rem_mb0[p]) : "r"(lm), "r"(p));
        }
    }
    __syncthreads();
    CLUSTER_SYNC();   // mbars + h bufs visible cluster-wide before step 0

    const unsigned mbA = smem_u32(&mb[0][0]);  // mb[r][par] = mbA + r*16 + par*8
    // this thread's two source barriers (by kseg)
    const unsigned srcA = mbA + (unsigned)((2 * kseg + 0) << 4);
    const unsigned srcB = mbA + (unsigned)((2 * kseg + 1) << 4);

    int gs = 0;
    for (int dir = 0; dir < 2; dir++) {
        const float* __restrict__ Wh = dir ? Wh_b : Wh_f;
        const float* __restrict__ xz = dir ? g_xz_b : g_xz_f;
        const int half = dir ? HID : 0;

        unsigned long long w2[32];
#pragma unroll
        for (int kk = 0; kk < 32; kk++) {
            union { float f[2]; unsigned long long u; } P;
            P.f[0] = Wh[(size_t)((kseg << 6) + 2 * kk + 0) * GATES + gc];
            P.f[1] = Wh[(size_t)((kseg << 6) + 2 * kk + 1) * GATES + gc];
            w2[kk] = P.u;
        }

        float xzp[4];
        if (isprod) {
            const int t0 = dir ? (T_STEPS - 1) : 0;
#pragma unroll
            for (int g = 0; g < 4; g++)
                xzp[g] = __ldcg(xz + ((size_t)t0 * BATCH + b0 + bp) * GATES
                                   + (g << 8) + jbase + jp);
        }

        for (int s = 0; s < T_STEPS; s++, gs++) {
            const int t   = dir ? (T_STEPS - 1 - s) : s;
            const int cur = gs & 1, nxt = cur ^ 1;
            const unsigned eoff = (unsigned)((gs & 1) << 3);

            // re-arm this step's 8 source barriers (lanes 0-7 of warp 0)
            if (tid < 8) {
                const unsigned myb = mbA + (unsigned)(tid << 4) + eoff;
                if (gs >= 2)   // ensure gs-2 phase of this buffer has passed
                    mbar_wait_cl(myb, (unsigned)(((gs - 2) >> 1) & 1));
                asm volatile(
                    "mbarrier.arrive.expect_tx.shared.b64 _, [%0], %1;"
                    :: "r"(myb), "r"(TXB) : "memory");
            }

            unsigned long long a0 = 0ull, a1 = 0ull;
            const float4* h0 = (const float4*)&h_s[cur][0][kseg << 6];
            const float4* h1 = (const float4*)&h_s[cur][1][kseg << 6];

            if (gs > 0) {   // wait only source 2*kseg (first 32 k)
                const int e = gs - 1;
                mbar_wait_cl(srcA + (unsigned)((e & 1) << 3),
                             (unsigned)((e >> 1) & 1));
            }
#pragma unroll
            for (int q = 0; q < 8; q++) {
                union { float4 f; unsigned long long u[2]; } U0, U1;
                U0.f = h0[q]; U1.f = h1[q];
                a0 = ffma2(U0.u[0], w2[2 * q + 0], a0);
                a0 = ffma2(U0.u[1], w2[2 * q + 1], a0);
                a1 = ffma2(U1.u[0], w2[2 * q + 0], a1);
                a1 = ffma2(U1.u[1], w2[2 * q + 1], a1);
            }
            if (gs > 0) {   // wait source 2*kseg+1 (second 32 k)
                const int e = gs - 1;
                mbar_wait_cl(srcB + (unsigned)((e & 1) << 3),
                             (unsigned)((e >> 1) & 1));
            }
#pragma unroll
            for (int q = 8; q < 16; q++) {
                union { float4 f; unsigned long long u[2]; } U0, U1;
                U0.f = h0[q]; U1.f = h1[q];
                a0 = ffma2(U0.u[0], w2[2 * q + 0], a0);
                a0 = ffma2(U0.u[1], w2[2 * q + 1], a0);
                a1 = ffma2(U1.u[0], w2[2 * q + 0], a1);
                a1 = ffma2(U1.u[1], w2[2 * q + 1], a1);
            }
            {
                union { unsigned long long u; float f[2]; } A0, A1;
                A0.u = a0; A1.u = a1;
                p_s[kseg][0][col] = A0.f[0] + A0.f[1];
                p_s[kseg][1][col] = A1.f[0] + A1.f[1];
            }
            __syncthreads();   // joins all warps' source waits + partials

            if (isprod) {
                float z[4];
#pragma unroll
                for (int g = 0; g < 4; g++) {
                    const int cc = (g << 5) + jp;
                    z[g] = xzp[g] + p_s[0][bp][cc] + p_s[1][bp][cc]
                                  + p_s[2][bp][cc] + p_s[3][bp][cc];
                }
                c_reg = fmaf(sigf(z[1]), c_reg, sigf(z[0]) * tanhf_(z[2]));
                const float h = sigf(z[3]) * tanhf_(c_reg);
                const unsigned hoff = (unsigned)(nxt << 11);  // buf stride 2048B
#pragma unroll
                for (int p = 0; p < CL_SZ; p++) {
                    asm volatile(
                        "st.async.shared::cluster.mbarrier::complete_tx::bytes.b32 "
                        "[%0], %1, [%2];"
                        :: "r"(rem_h0[p] + hoff), "r"(__float_as_uint(h)),
                           "r"(rem_mb0[p] + eoff) : "memory");
                }
                g_houts[((size_t)t * BATCH + b0 + bp) * (2 * HID)
                        + half + jbase + jp] = h;
                if (s + 1 < T_STEPS) {
                    const int tn = dir ? (T_STEPS - 2 - s) : (s + 1);
#pragma unroll
                    for (int g = 0; g < 4; g++)
                        xzp[g] = __ldcg(xz + ((size_t)tn * BATCH + b0 + bp) * GATES
                                           + (g << 8) + jbase + jp);
                }
            }
        }
    }
    // drain final exchange (e = 8191) on all 8 source barriers
    {
        const int e = 2 * T_STEPS - 1;
        if (tid < 8)
            mbar_wait_cl(mbA + (unsigned)(tid << 4) + (unsigned)((e & 1) << 3),
                         (unsigned)((e >> 1) & 1));
    }
    __syncthreads();
    CLUSTER_SYNC();
}

// ---------------- launch ----------------------------------------------------
extern "C" void kernel_launch(void* const* d_in, const int* in_sizes, int n_in,
                              void* d_out, int out_size) {
    const float* carry_c = (const float*)d_in[0];
    const float* carry_h = (const float*)d_in[1];
    const float* x       = (const float*)d_in[2];
    const float* Wx_f    = (const float*)d_in[3];
    const float* Wh_f    = (const float*)d_in[4];
    const float* b_f     = (const float*)d_in[5];
    const float* Wx_b    = (const float*)d_in[6];
    const float* Wh_b    = (const float*)d_in[7];
    const float* b_b     = (const float*)d_in[8];
    const float* W_dense = (const float*)d_in[9];
    const float* b_dense = (const float*)d_in[10];
    float* out = (float*)d_out;

    float* xz_f; cudaGetSymbolAddress((void**)&xz_f, g_xz_f);
    float* xz_b; cudaGetSymbolAddress((void**)&xz_b, g_xz_b);

    k_prof_pad<<<1, 1>>>();   // aligns ncu capture window onto k_recur

    dim3 g1(GATES / 128, (BATCH * T_STEPS) / 128);
    k_gemm_xz<<<g1, 256>>>(x, Wx_f, b_f, xz_f);
    k_gemm_xz<<<g1, 256>>>(x, Wx_b, b_b, xz_b);

    k_recur<<<NBLK, 512>>>(carry_c, carry_h, Wh_f, Wh_b);

    dim3 g2(OUTD / 128, (BATCH * T_STEPS) / 128);
    k_gemm_dense<<<g2, 256>>>(W_dense, b_dense, out);
}

// round 17
// speedup vs baseline: 3.4967x; 1.0735x over previous
#include <cuda_runtime.h>
#include <math.h>

#define T_STEPS 4096
#define BATCH   32
#define DIN     256
#define HID     256
#define GATES   1024
#define OUTD    512
#define CL_SZ   8
#define NBLK    128

__device__ float g_xz_f[(size_t)T_STEPS * BATCH * GATES];
__device__ float g_xz_b[(size_t)T_STEPS * BATCH * GATES];
__device__ float g_houts[(size_t)T_STEPS * BATCH * 2 * HID];

__device__ __forceinline__ float sigf(float x)  { return 1.0f / (1.0f + __expf(-x)); }
__device__ __forceinline__ float tanhf_(float x){ return 1.0f - 2.0f / (__expf(2.0f * x) + 1.0f); }

__device__ __forceinline__ unsigned long long ffma2(
    unsigned long long a, unsigned long long b, unsigned long long c) {
    unsigned long long d;
    asm("fma.rn.f32x2 %0, %1, %2, %3;" : "=l"(d) : "l"(a), "l"(b), "l"(c));
    return d;
}
__device__ __forceinline__ unsigned long long bcast2(float a) {
    unsigned long long d;
    asm("mov.b64 %0, {%1, %1};" : "=l"(d) : "f"(a));
    return d;
}
__device__ __forceinline__ unsigned smem_u32(const void* p) {
    return (unsigned)__cvta_generic_to_shared(p);
}
// CTA-scoped acquire wait. Data arrives in LOCAL smem via st.async's async
// proxy with complete_tx on the LOCAL mbarrier — same consumer pattern as
// TMA, which uses acquire.cta. Cluster-scoped acquire (used in all prior
// rounds) forces a fence-scope >= cluster per wait => CCTL.IVALL-class L1
// work by every waiting warp every step; suspected dominant step cost.
__device__ __forceinline__ void mbar_wait_cta(unsigned addr, unsigned parity) {
    asm volatile(
        "{\n\t.reg .pred P;\n"
        "LW%=:\n\t"
        "mbarrier.try_wait.parity.acquire.cta.shared::cta.b64 P, [%0], %1, 0x989680;\n\t"
        "@P bra LD%=;\n\t"
        "bra LW%=;\n"
        "LD%=:\n\t}"
        :: "r"(addr), "r"(parity) : "memory");
}

#define CLUSTER_SYNC() do { \
    asm volatile("barrier.cluster.arrive.aligned;" ::: "memory"); \
    asm volatile("barrier.cluster.wait.aligned;"   ::: "memory"); \
} while (0)

// dummy launch to align ncu's capture window (-s 5 -c 1) onto k_recur
__global__ void k_prof_pad() {}

// ---------------- GEMM 1: xz = x @ Wx + bias (unchanged, passing) -----------
__global__ void __launch_bounds__(256) k_gemm_xz(
    const float* __restrict__ A, const float* __restrict__ W,
    const float* __restrict__ bias, float* __restrict__ C)
{
    __shared__ float As[8][128];
    __shared__ float Bs[8][128];
    const int tid = threadIdx.x;
    const int n0 = blockIdx.x << 7, m0 = blockIdx.y << 7;
    const int am = tid >> 1, ak = (tid & 1) << 2;
    const int bk = tid >> 5, bn = (tid & 31) << 2;
    const int ty = tid >> 4, tx = tid & 15;
    unsigned long long acc2[8][4] = {};

    for (int k0 = 0; k0 < DIN; k0 += 8) {
        float4 av = *(const float4*)(A + (size_t)(m0 + am) * DIN + k0 + ak);
        float4 bv = *(const float4*)(W + (size_t)(k0 + bk) * GATES + n0 + bn);
        __syncthreads();
        As[ak + 0][am] = av.x; As[ak + 1][am] = av.y;
        As[ak + 2][am] = av.z; As[ak + 3][am] = av.w;
        *(float4*)&Bs[bk][bn] = bv;
        __syncthreads();
#pragma unroll
        for (int kk = 0; kk < 8; kk++) {
            float ar[8];
            *(float4*)&ar[0] = *(const float4*)&As[kk][(ty << 3) + 0];
            *(float4*)&ar[4] = *(const float4*)&As[kk][(ty << 3) + 4];
            union { float4 f; unsigned long long u[2]; } B0, B1;
            B0.f = *(const float4*)&Bs[kk][(tx << 3) + 0];
            B1.f = *(const float4*)&Bs[kk][(tx << 3) + 4];
#pragma unroll
            for (int r = 0; r < 8; r++) {
                unsigned long long a2 = bcast2(ar[r]);
                acc2[r][0] = ffma2(a2, B0.u[0], acc2[r][0]);
                acc2[r][1] = ffma2(a2, B0.u[1], acc2[r][1]);
                acc2[r][2] = ffma2(a2, B1.u[0], acc2[r][2]);
                acc2[r][3] = ffma2(a2, B1.u[1], acc2[r][3]);
            }
        }
    }
    float bi[8];
    *(float4*)&bi[0] = *(const float4*)(bias + n0 + (tx << 3) + 0);
    *(float4*)&bi[4] = *(const float4*)(bias + n0 + (tx << 3) + 4);
#pragma unroll
    for (int r = 0; r < 8; r++) {
        int m = m0 + (ty << 3) + r;
        int t = m & (T_STEPS - 1), b = m >> 12;
        float* dst = C + (size_t)(t * BATCH + b) * GATES + n0 + (tx << 3);
        union { unsigned long long u; float f[2]; } U;
        float o[8];
#pragma unroll
        for (int c4 = 0; c4 < 4; c4++) {
            U.u = acc2[r][c4];
            o[2 * c4 + 0] = U.f[0] + bi[2 * c4 + 0];
            o[2 * c4 + 1] = U.f[1] + bi[2 * c4 + 1];
        }
        *(float4*)(dst + 0) = *(float4*)&o[0];
        *(float4*)(dst + 4) = *(float4*)&o[4];
    }
}

// ---------------- GEMM 2: out = relu(h_cat) @ W_dense + b (unchanged) ------
__global__ void __launch_bounds__(256) k_gemm_dense(
    const float* __restrict__ W, const float* __restrict__ bias,
    float* __restrict__ out)
{
    __shared__ float As[8][128];
    __shared__ float Bs[8][128];
    const int tid = threadIdx.x;
    const int n0 = blockIdx.x << 7, m0 = blockIdx.y << 7;
    const int am = tid >> 1, ak = (tid & 1) << 2;
    const int bk = tid >> 5, bn = (tid & 31) << 2;
    const int ty = tid >> 4, tx = tid & 15;
    unsigned long long acc2[8][4] = {};

    for (int k0 = 0; k0 < 2 * HID; k0 += 8) {
        float4 av = *(const float4*)(g_houts + (size_t)(m0 + am) * (2 * HID) + k0 + ak);
        av.x = fmaxf(av.x, 0.f); av.y = fmaxf(av.y, 0.f);
        av.z = fmaxf(av.z, 0.f); av.w = fmaxf(av.w, 0.f);
        float4 bv = *(const float4*)(W + (size_t)(k0 + bk) * OUTD + n0 + bn);
        __syncthreads();
        As[ak + 0][am] = av.x; As[ak + 1][am] = av.y;
        As[ak + 2][am] = av.z; As[ak + 3][am] = av.w;
        *(float4*)&Bs[bk][bn] = bv;
        __syncthreads();
#pragma unroll
        for (int kk = 0; kk < 8; kk++) {
            float ar[8];
            *(float4*)&ar[0] = *(const float4*)&As[kk][(ty << 3) + 0];
            *(float4*)&ar[4] = *(const float4*)&As[kk][(ty << 3) + 4];
            union { float4 f; unsigned long long u[2]; } B0, B1;
            B0.f = *(const float4*)&Bs[kk][(tx << 3) + 0];
            B1.f = *(const float4*)&Bs[kk][(tx << 3) + 4];
#pragma unroll
            for (int r = 0; r < 8; r++) {
                unsigned long long a2 = bcast2(ar[r]);
                acc2[r][0] = ffma2(a2, B0.u[0], acc2[r][0]);
                acc2[r][1] = ffma2(a2, B0.u[1], acc2[r][1]);
                acc2[r][2] = ffma2(a2, B1.u[0], acc2[r][2]);
                acc2[r][3] = ffma2(a2, B1.u[1], acc2[r][3]);
            }
        }
    }
    float bi[8];
    *(float4*)&bi[0] = *(const float4*)(bias + n0 + (tx << 3) + 0);
    *(float4*)&bi[4] = *(const float4*)(bias + n0 + (tx << 3) + 4);
#pragma unroll
    for (int r = 0; r < 8; r++) {
        int m = m0 + (ty << 3) + r;
        int b = m & 31, t = m >> 5;
        float* dst = out + ((size_t)b * T_STEPS + t) * OUTD + n0 + (tx << 3);
        union { unsigned long long u; float f[2]; } U;
        float o[8];
#pragma unroll
        for (int c4 = 0; c4 < 4; c4++) {
            U.u = acc2[r][c4];
            o[2 * c4 + 0] = U.f[0] + bi[2 * c4 + 0];
            o[2 * c4 + 1] = U.f[1] + bi[2 * c4 + 1];
        }
        *(float4*)(dst + 0) = *(float4*)&o[0];
        *(float4*)(dst + 4) = *(float4*)&o[4];
    }
}

// ---------------- Recurrence: R10 protocol, CTA-scoped waits ---------------
// Byte-identical to the 22.9ms best EXCEPT mbarrier waits use acquire.cta
// instead of acquire.cluster (single-variable test of the per-wait
// cluster-scope L1-flush theory).
__global__ void __cluster_dims__(CL_SZ, 1, 1) __launch_bounds__(512, 1) k_recur(
    const float* __restrict__ carry_c, const float* __restrict__ carry_h,
    const float* __restrict__ Wh_f, const float* __restrict__ Wh_b)
{
    __shared__ float h_s[2][2][HID];           // ping-pong: 2048 B apart
    __shared__ float p_s[4][2][128];
    __shared__ unsigned long long mb[2];       // 8 B apart

    const int tid   = threadIdx.x;
    const int rank  = blockIdx.x & (CL_SZ - 1);
    const int b0    = (blockIdx.x >> 3) << 1;
    const int jbase = rank << 5;

    const int kseg = tid >> 7;
    const int col  = tid & 127;
    const int gate = col >> 5, jl = col & 31;
    const int gc   = (gate << 8) + jbase + jl;

    const bool isprod = (tid >= 448);          // warps 14-15
    const int  pt = tid - 448;
    const int  bp = pt >> 5, jp = pt & 31;
    const unsigned TXB = CL_SZ * 64u * 4u;     // 2048 bytes per exchange

    h_s[0][tid >> 8][tid & 255] =
        carry_h[(size_t)(b0 + (tid >> 8)) * HID + (tid & 255)];

    if (tid == 0) {
        asm volatile("mbarrier.init.shared.b64 [%0], %1;"
                     :: "r"(smem_u32(&mb[0])), "r"(1) : "memory");
        asm volatile("mbarrier.init.shared.b64 [%0], %1;"
                     :: "r"(smem_u32(&mb[1])), "r"(1) : "memory");
    }

    float c_reg = 0.f;
    unsigned rem_h0[CL_SZ];   // peer addr of h_s[0][bp][jbase+jp]; buf1 = +2048
    unsigned rem_mb0[CL_SZ];  // peer addr of mb[0]; mb[1] = +8
    if (isprod) {
        c_reg = carry_c[(size_t)(b0 + bp) * HID + jbase + jp];
        unsigned lh = smem_u32(&h_s[0][bp][jbase + jp]);
        unsigned lm = smem_u32(&mb[0]);
#pragma unroll
        for (int p = 0; p < CL_SZ; p++) {
            asm("mapa.shared::cluster.u32 %0, %1, %2;"
                : "=r"(rem_h0[p]) : "r"(lh), "r"(p));
            asm("mapa.shared::cluster.u32 %0, %1, %2;"
                : "=r"(rem_mb0[p]) : "r"(lm), "r"(p));
        }
    }
    __syncthreads();
    CLUSTER_SYNC();   // mbars + h bufs visible cluster-wide before step 0

    const unsigned mb0a = smem_u32(&mb[0]);

    int gs = 0;
    for (int dir = 0; dir < 2; dir++) {
        const float* __restrict__ Wh = dir ? Wh_b : Wh_f;
        const float* __restrict__ xz = dir ? g_xz_b : g_xz_f;
        const int half = dir ? HID : 0;

        unsigned long long w2[32];
#pragma unroll
        for (int kk = 0; kk < 32; kk++) {
            union { float f[2]; unsigned long long u; } P;
            P.f[0] = Wh[(size_t)((kseg << 6) + 2 * kk + 0) * GATES + gc];
            P.f[1] = Wh[(size_t)((kseg << 6) + 2 * kk + 1) * GATES + gc];
            w2[kk] = P.u;
        }

        float xzp[4];
        if (isprod) {
            const int t0 = dir ? (T_STEPS - 1) : 0;
#pragma unroll
            for (int g = 0; g < 4; g++)
                xzp[g] = __ldcg(xz + ((size_t)t0 * BATCH + b0 + bp) * GATES
                                   + (g << 8) + jbase + jp);
        }

        for (int s = 0; s < T_STEPS; s++, gs++) {
            const int t   = dir ? (T_STEPS - 1 - s) : s;
            const int cur = gs & 1, nxt = cur ^ 1;

            if (gs > 0) {   // wait for exchange gs-1 (all 2048 B landed)
                const int e = gs - 1;
                mbar_wait_cta(mb0a + (unsigned)((e & 1) << 3),
                              (unsigned)((e >> 1) & 1));
            }
            // declare this step's expected exchange bytes (one thread)
            if (tid == 448)
                asm volatile(
                    "mbarrier.arrive.expect_tx.shared.b64 _, [%0], %1;"
                    :: "r"(mb0a + (unsigned)((gs & 1) << 3)), "r"(TXB)
                    : "memory");

            unsigned long long a0 = 0ull, a1 = 0ull;
            {
                const float4* h0 = (const float4*)&h_s[cur][0][kseg << 6];
                const float4* h1 = (const float4*)&h_s[cur][1][kseg << 6];
#pragma unroll
                for (int q = 0; q < 16; q++) {
                    union { float4 f; unsigned long long u[2]; } U0, U1;
                    U0.f = h0[q]; U1.f = h1[q];
                    a0 = ffma2(U0.u[0], w2[2 * q + 0], a0);
                    a0 = ffma2(U0.u[1], w2[2 * q + 1], a0);
                    a1 = ffma2(U1.u[0], w2[2 * q + 0], a1);
                    a1 = ffma2(U1.u[1], w2[2 * q + 1], a1);
                }
            }
            {
                union { unsigned long long u; float f[2]; } A0, A1;
                A0.u = a0; A1.u = a1;
                p_s[kseg][0][col] = A0.f[0] + A0.f[1];
                p_s[kseg][1][col] = A1.f[0] + A1.f[1];
            }
            __syncthreads();

            if (isprod) {
                float z[4];
#pragma unroll
                for (int g = 0; g < 4; g++) {
                    const int cc = (g << 5) + jp;
                    z[g] = xzp[g] + p_s[0][bp][cc] + p_s[1][bp][cc]
                                  + p_s[2][bp][cc] + p_s[3][bp][cc];
                }
                c_reg = fmaf(sigf(z[1]), c_reg, sigf(z[0]) * tanhf_(z[2]));
                const float h = sigf(z[3]) * tanhf_(c_reg);
                const unsigned hoff = (unsigned)(nxt << 11);     // buf stride 2048B
                const unsigned moff = (unsigned)((gs & 1) << 3); // mbar stride 8B
#pragma unroll
                for (int p = 0; p < CL_SZ; p++) {
                    asm volatile(
                        "st.async.shared::cluster.mbarrier::complete_tx::bytes.b32 "
                        "[%0], %1, [%2];"
                        :: "r"(rem_h0[p] + hoff), "r"(__float_as_uint(h)),
                           "r"(rem_mb0[p] + moff) : "memory");
                }
                g_houts[((size_t)t * BATCH + b0 + bp) * (2 * HID)
                        + half + jbase + jp] = h;
                if (s + 1 < T_STEPS) {
                    const int tn = dir ? (T_STEPS - 2 - s) : (s + 1);
#pragma unroll
                    for (int g = 0; g < 4; g++)
                        xzp[g] = __ldcg(xz + ((size_t)tn * BATCH + b0 + bp) * GATES
                                           + (g << 8) + jbase + jp);
                }
            }
            // no second syncthreads: st.async carries data + signal together
        }
    }
    // drain the final exchange so no in-flight st.async targets exiting CTAs
    {
        const int e = 2 * T_STEPS - 1;
        mbar_wait_cta(mb0a + (unsigned)((e & 1) << 3), (unsigned)((e >> 1) & 1));
    }
    CLUSTER_SYNC();
}

// ---------------- launch ----------------------------------------------------
extern "C" void kernel_launch(void* const* d_in, const int* in_sizes, int n_in,
                              void* d_out, int out_size) {
    const float* carry_c = (const float*)d_in[0];
    const float* carry_h = (const float*)d_in[1];
    const float* x       = (const float*)d_in[2];
    const float* Wx_f    = (const float*)d_in[3];
    const float* Wh_f    = (const float*)d_in[4];
    const float* b_f     = (const float*)d_in[5];
    const float* Wx_b    = (const float*)d_in[6];
    const float* Wh_b    = (const float*)d_in[7];
    const float* b_b     = (const float*)d_in[8];
    const float* W_dense = (const float*)d_in[9];
    const float* b_dense = (const float*)d_in[10];
    float* out = (float*)d_out;

    float* xz_f; cudaGetSymbolAddress((void**)&xz_f, g_xz_f);
    float* xz_b; cudaGetSymbolAddress((void**)&xz_b, g_xz_b);

    k_prof_pad<<<1, 1>>>();   // aligns ncu capture window onto k_recur

    dim3 g1(GATES / 128, (BATCH * T_STEPS) / 128);
    k_gemm_xz<<<g1, 256>>>(x, Wx_f, b_f, xz_f);
    k_gemm_xz<<<g1, 256>>>(x, Wx_b, b_b, xz_b);

    k_recur<<<NBLK, 512>>>(carry_c, carry_h, Wh_f, Wh_b);

    dim3 g2(OUTD / 128, (BATCH * T_STEPS) / 128);
    k_gemm_dense<<<g2, 256>>>(W_dense, b_dense, out);
}